// round 10
// baseline (speedup 1.0000x reference)
#include <cuda_runtime.h>
#include <cstdint>

// ---------------------------------------------------------------------------
// MultiHeadAttention w/ Shaw relative position. B=2, L=2048, E=1024, H=16,
// hd=64, clip=16.  compute_103 path -> mma.sync.m16n8k8 tf32 tensor cores.
//  1) q/k/v projections + ReLU: mma.sync tf32 GEMM -> split-head [BH][L][64]
//  2) flash attention (qrel fused): S=QK^T / O=PV on mma.sync; softmax is
//     MUFU-bound -> hybrid exp (2/3 MUFU.EX2, 1/3 FMA-pipe polynomial).
//     CTA = 64 q-rows x 64 k-tile, 256 threads, 2 CTA/SM.
//  3) out projection + ReLU: mma.sync tf32 GEMM
// ---------------------------------------------------------------------------

#define BATCH  2
#define SEQ    2048
#define EMB    1024
#define NHEADS 16
#define HDIM   64
#define DKEY   1024
#define CLIPV  16
#define ND     33
#define MROWS  (BATCH*SEQ)
#define BH     (BATCH*NHEADS)

__device__ __align__(256) float g_qh[BH*SEQ*HDIM];
__device__ __align__(256) float g_kh[BH*SEQ*HDIM];
__device__ __align__(256) float g_vh[BH*SEQ*HDIM];
__device__ __align__(256) float g_ctx[MROWS*DKEY];

__device__ __forceinline__ float tf32r(float x) {
    asm("cvt.rna.tf32.f32 %0, %0;" : "+f"(x));
    return x;
}
__device__ __forceinline__ void mma_tf32(
    float& d0, float& d1, float& d2, float& d3,
    uint32_t a0, uint32_t a1, uint32_t a2, uint32_t a3,
    uint32_t b0, uint32_t b1)
{
    asm volatile(
        "mma.sync.aligned.m16n8k8.row.col.f32.tf32.tf32.f32 "
        "{%0,%1,%2,%3}, {%4,%5,%6,%7}, {%8,%9}, {%0,%1,%2,%3};"
        : "+f"(d0), "+f"(d1), "+f"(d2), "+f"(d3)
        : "r"(a0), "r"(a1), "r"(a2), "r"(a3), "r"(b0), "r"(b1));
}

// exp(x) for x <= 0 on the FMA/ALU pipes only (no MUFU).
// 2^y via magic-number split + degree-5 Taylor on [-0.5,0.5]; err ~2.4e-6.
__device__ __forceinline__ float fexp(float x) {
    float y = x * 1.44269504f;
    y = fmaxf(y, -126.0f);
    float z = y + 12582912.0f;               // round-to-nearest integer
    int   i = __float_as_int(z) - 0x4B400000;
    float f = y - (z - 12582912.0f);         // [-0.5, 0.5]
    float p = 1.33335581e-3f;
    p = fmaf(p, f, 9.61812910e-3f);
    p = fmaf(p, f, 5.55041087e-2f);
    p = fmaf(p, f, 2.40226507e-1f);
    p = fmaf(p, f, 6.93147182e-1f);
    p = fmaf(p, f, 1.0f);
    return __int_as_float(__float_as_int(p) + (i << 23));
}

// ---------------------------------------------------------------------------
// mma.sync tf32 GEMM projections (validated R7). CTA 128x128, BK=16.
// ---------------------------------------------------------------------------
#define PM_PAD 20
#define PM_BUF (128 * PM_PAD)
#define PSMEM  (4 * PM_BUF * 4)

__global__ void __launch_bounds__(256) proj_mma(
    const float* __restrict__ X, const float* __restrict__ W,
    const float* __restrict__ bias, float* __restrict__ out, int split)
{
    extern __shared__ float smf[];
    float* As = smf;
    float* Bs = smf + 2 * PM_BUF;

    const int tid = threadIdx.x;
    const int lane = tid & 31, wid = tid >> 5;
    const int wm = wid & 3, wn = wid >> 2;
    const int lr = lane >> 2, lq = lane & 3;
    const int m0 = blockIdx.y * 128, n0 = blockIdx.x * 128;

    const float4* X4 = (const float4*)X;
    const float4* W4 = (const float4*)W;

    const int r0 = tid >> 2, c0 = tid & 3;
    const int r1 = (tid + 256) >> 2, c1 = tid & 3;

    float c[2][8][4];
    #pragma unroll
    for (int i = 0; i < 2; i++)
        #pragma unroll
        for (int j = 0; j < 8; j++)
            #pragma unroll
            for (int t = 0; t < 4; t++) c[i][j][t] = 0.f;

    {
        float4 xa0 = X4[(size_t)(m0 + r0) * 256 + c0];
        float4 xa1 = X4[(size_t)(m0 + r1) * 256 + c1];
        float4 wb0 = W4[(size_t)(n0 + r0) * 256 + c0];
        float4 wb1 = W4[(size_t)(n0 + r1) * 256 + c1];
        float* a = As; float* b = Bs;
        a[r0*PM_PAD + c0*4+0] = tf32r(xa0.x); a[r0*PM_PAD + c0*4+1] = tf32r(xa0.y);
        a[r0*PM_PAD + c0*4+2] = tf32r(xa0.z); a[r0*PM_PAD + c0*4+3] = tf32r(xa0.w);
        a[r1*PM_PAD + c1*4+0] = tf32r(xa1.x); a[r1*PM_PAD + c1*4+1] = tf32r(xa1.y);
        a[r1*PM_PAD + c1*4+2] = tf32r(xa1.z); a[r1*PM_PAD + c1*4+3] = tf32r(xa1.w);
        b[r0*PM_PAD + c0*4+0] = tf32r(wb0.x); b[r0*PM_PAD + c0*4+1] = tf32r(wb0.y);
        b[r0*PM_PAD + c0*4+2] = tf32r(wb0.z); b[r0*PM_PAD + c0*4+3] = tf32r(wb0.w);
        b[r1*PM_PAD + c1*4+0] = tf32r(wb1.x); b[r1*PM_PAD + c1*4+1] = tf32r(wb1.y);
        b[r1*PM_PAD + c1*4+2] = tf32r(wb1.z); b[r1*PM_PAD + c1*4+3] = tf32r(wb1.w);
    }
    __syncthreads();

    for (int kc = 0; kc < 64; kc++) {
        const int buf = kc & 1;
        float4 xa0, xa1, wb0, wb1;
        if (kc + 1 < 64) {
            const int kb = (kc + 1) * 4;
            xa0 = X4[(size_t)(m0 + r0) * 256 + kb + c0];
            xa1 = X4[(size_t)(m0 + r1) * 256 + kb + c1];
            wb0 = W4[(size_t)(n0 + r0) * 256 + kb + c0];
            wb1 = W4[(size_t)(n0 + r1) * 256 + kb + c1];
        }

        const float* a = As + buf * PM_BUF;
        const float* b = Bs + buf * PM_BUF;
        #pragma unroll
        for (int ks = 0; ks < 2; ks++) {
            const int k0 = ks * 8 + lq;
            uint32_t af[2][4];
            #pragma unroll
            for (int mt = 0; mt < 2; mt++) {
                const int row = wm * 32 + mt * 16 + lr;
                af[mt][0] = __float_as_uint(a[row * PM_PAD + k0]);
                af[mt][1] = __float_as_uint(a[(row + 8) * PM_PAD + k0]);
                af[mt][2] = __float_as_uint(a[row * PM_PAD + k0 + 4]);
                af[mt][3] = __float_as_uint(a[(row + 8) * PM_PAD + k0 + 4]);
            }
            #pragma unroll
            for (int nt = 0; nt < 8; nt++) {
                const int col = wn * 64 + nt * 8 + lr;
                uint32_t b0 = __float_as_uint(b[col * PM_PAD + k0]);
                uint32_t b1 = __float_as_uint(b[col * PM_PAD + k0 + 4]);
                #pragma unroll
                for (int mt = 0; mt < 2; mt++)
                    mma_tf32(c[mt][nt][0], c[mt][nt][1], c[mt][nt][2], c[mt][nt][3],
                             af[mt][0], af[mt][1], af[mt][2], af[mt][3], b0, b1);
            }
        }

        if (kc + 1 < 64) {
            float* an = As + (buf ^ 1) * PM_BUF;
            float* bn = Bs + (buf ^ 1) * PM_BUF;
            an[r0*PM_PAD + c0*4+0] = tf32r(xa0.x); an[r0*PM_PAD + c0*4+1] = tf32r(xa0.y);
            an[r0*PM_PAD + c0*4+2] = tf32r(xa0.z); an[r0*PM_PAD + c0*4+3] = tf32r(xa0.w);
            an[r1*PM_PAD + c1*4+0] = tf32r(xa1.x); an[r1*PM_PAD + c1*4+1] = tf32r(xa1.y);
            an[r1*PM_PAD + c1*4+2] = tf32r(xa1.z); an[r1*PM_PAD + c1*4+3] = tf32r(xa1.w);
            bn[r0*PM_PAD + c0*4+0] = tf32r(wb0.x); bn[r0*PM_PAD + c0*4+1] = tf32r(wb0.y);
            bn[r0*PM_PAD + c0*4+2] = tf32r(wb0.z); bn[r0*PM_PAD + c0*4+3] = tf32r(wb0.w);
            bn[r1*PM_PAD + c1*4+0] = tf32r(wb1.x); bn[r1*PM_PAD + c1*4+1] = tf32r(wb1.y);
            bn[r1*PM_PAD + c1*4+2] = tf32r(wb1.z); bn[r1*PM_PAD + c1*4+3] = tf32r(wb1.w);
        }
        __syncthreads();
    }

    #pragma unroll
    for (int mt = 0; mt < 2; mt++) {
        #pragma unroll
        for (int nt = 0; nt < 8; nt++) {
            const int row = m0 + wm * 32 + mt * 16 + lr;
            const int col = n0 + wn * 64 + nt * 8 + 2 * lq;
            const float bia0 = bias[col], bia1 = bias[col + 1];
            #pragma unroll
            for (int half = 0; half < 2; half++) {
                const int m = row + half * 8;
                float v0 = fmaxf(c[mt][nt][half * 2 + 0] + bia0, 0.f);
                float v1 = fmaxf(c[mt][nt][half * 2 + 1] + bia1, 0.f);
                if (split) {
                    const int bb = m >> 11, ll = m & (SEQ - 1);
                    const int h = col >> 6, d = col & 63;
                    out[(((size_t)(bb * NHEADS + h)) * SEQ + ll) * HDIM + d]     = v0;
                    out[(((size_t)(bb * NHEADS + h)) * SEQ + ll) * HDIM + d + 1] = v1;
                } else {
                    float2 v = make_float2(v0, v1);
                    *(float2*)&out[(size_t)m * DKEY + col] = v;
                }
            }
        }
    }
}

// ---------------------------------------------------------------------------
// Flash attention on mma.sync tf32, qrel fused, hybrid exp.
// CTA: 64 q-rows x 64 k-tile, 256 thr = 8 warps (4 rowgroups x 2 halves).
// Pads: Q/K/P stride 68 (frag residues 4g+t), V stride 72 (8t+g).
// ---------------------------------------------------------------------------
#define KPAD 68
#define VPAD 72
#define AS_Q  0
#define AS_K  4352
#define AS_V  8704
#define AS_P  13312
#define AS_QR 17664
#define AS_RB 19776
#define AS_RV 21824
#define AS_CR 23936
#define AS_TOT 24000        // floats -> 96000 bytes, 2 CTA/SM

__global__ void __launch_bounds__(256, 2) attn_mma(
    const float* __restrict__ rel_k, const float* __restrict__ rel_v)
{
    extern __shared__ float smf[];
    float* Qs = smf + AS_Q;
    float* Ks = smf + AS_K;
    float* Vs = smf + AS_V;
    float* Ps = smf + AS_P;
    float* QR = smf + AS_QR;
    float* RB = smf + AS_RB;
    float* RV = smf + AS_RV;
    float* CR = smf + AS_CR;

    const int tid = threadIdx.x;
    const int lane = tid & 31, wid = tid >> 5;
    const int g = lane >> 2, t = lane & 3;
    const int rg = wid >> 1;          // row group (16 rows)
    const int cg = wid & 1;           // column half
    const int bh = blockIdx.y, q0 = blockIdx.x * 64;
    const int sq = tid >> 2;          // softmax row
    const int seg = tid & 3;          // 16-col segment

    // ---- prologue: Q (tf32, vectorized), rel_k -> Ps temp, rel_v, RB=-inf
    const float4* q4 = (const float4*)(g_qh + ((size_t)bh * SEQ + q0) * HDIM);
    for (int i = tid; i < 1024; i += 256) {
        int r = i >> 4, cc = (i & 15) << 2;
        float4 v = q4[i];
        v.x = tf32r(v.x); v.y = tf32r(v.y); v.z = tf32r(v.z); v.w = tf32r(v.w);
        *(float4*)&Qs[r*KPAD + cc] = v;
    }
    const float4* rk4 = (const float4*)rel_k;
    const float4* rv4 = (const float4*)rel_v;
    for (int i = tid; i < ND * 16; i += 256) {
        int r = i >> 4, cc = (i & 15) << 2;
        *(float4*)&Ps[r*KPAD + cc] = rk4[i];
        ((float4*)RV)[i] = rv4[i];
    }
    for (int i = tid; i < 64 * 32; i += 256) RB[i] = -1e30f;
    __syncthreads();

    // ---- fused qrel: QR[q][d] = Qs[q][:] . rel_k[d][:]
    for (int i = tid; i < 64 * ND; i += 256) {
        int q = i / ND, d = i - q * ND;
        float s = 0.f;
        #pragma unroll 8
        for (int cc = 0; cc < 64; cc++) s = fmaf(Qs[q*KPAD + cc], Ps[d*KPAD + cc], s);
        QR[q*ND + d] = s;
    }

    // ---- preload Q fragments (warp rows rg*16 + {g, g+8})
    uint32_t qa[8][4];
    {
        const int rb = rg * 16;
        #pragma unroll
        for (int ks = 0; ks < 8; ks++) {
            qa[ks][0] = __float_as_uint(Qs[(rb+g  )*KPAD + ks*8 + t    ]);
            qa[ks][1] = __float_as_uint(Qs[(rb+g+8)*KPAD + ks*8 + t    ]);
            qa[ks][2] = __float_as_uint(Qs[(rb+g  )*KPAD + ks*8 + t + 4]);
            qa[ks][3] = __float_as_uint(Qs[(rb+g+8)*KPAD + ks*8 + t + 4]);
        }
    }

    float o[4][4] = {};
    float mrow = -1e30f, lrow = 0.f, slo = 0.f, shi = 0.f;

    for (int kt = 0; kt < SEQ / 64; kt++) {
        // ---- stage K, V (tf32, vectorized)
        const float4* k4 = (const float4*)(g_kh + ((size_t)bh * SEQ + kt*64) * HDIM);
        const float4* v4 = (const float4*)(g_vh + ((size_t)bh * SEQ + kt*64) * HDIM);
        for (int i = tid; i < 1024; i += 256) {
            int r = i >> 4, cc = (i & 15) << 2;
            float4 kv = k4[i];
            kv.x = tf32r(kv.x); kv.y = tf32r(kv.y); kv.z = tf32r(kv.z); kv.w = tf32r(kv.w);
            *(float4*)&Ks[r*KPAD + cc] = kv;
            float4 vv = v4[i];
            vv.x = tf32r(vv.x); vv.y = tf32r(vv.y); vv.z = tf32r(vv.z); vv.w = tf32r(vv.w);
            *(float4*)&Vs[r*VPAD + cc] = vv;
        }
        __syncthreads();   // also orders prologue QR compute before Ps reuse

        // ---- S = Q K^T  (warp: 16 rows x 32 cols)
        float s[4][4] = {};
        #pragma unroll
        for (int ks = 0; ks < 8; ks++) {
            #pragma unroll
            for (int nt = 0; nt < 4; nt++) {
                const int col = cg*32 + nt*8 + g;
                uint32_t b0 = __float_as_uint(Ks[col*KPAD + ks*8 + t    ]);
                uint32_t b1 = __float_as_uint(Ks[col*KPAD + ks*8 + t + 4]);
                mma_tf32(s[nt][0], s[nt][1], s[nt][2], s[nt][3],
                         qa[ks][0], qa[ks][1], qa[ks][2], qa[ks][3], b0, b1);
            }
        }
        {
            const int r0 = rg*16 + g;
            #pragma unroll
            for (int nt = 0; nt < 4; nt++) {
                const int col = cg*32 + nt*8 + 2*t;
                *(float2*)&Ps[ r0     *KPAD + col] = make_float2(s[nt][0], s[nt][1]);
                *(float2*)&Ps[(r0 + 8)*KPAD + col] = make_float2(s[nt][2], s[nt][3]);
            }
        }
        __syncthreads();

        // ---- softmax + Shaw-rel bookkeeping (thread = row sq, 16 cols)
        {
            const int kb = kt*64 + seg*16;
            const int qg = q0 + sq;
            float sv[16];
            #pragma unroll
            for (int u = 0; u < 4; u++)
                *(float4*)&sv[u*4] = *(const float4*)&Ps[sq*KPAD + seg*16 + u*4];
            float tmax = -1e30f;
            #pragma unroll
            for (int j = 0; j < 16; j++) {
                int diff = kb + j - qg;
                int dcl = diff < -CLIPV ? 0 : (diff > CLIPV ? 2*CLIPV : diff + CLIPV);
                float v = (sv[j] + QR[sq*ND + dcl]) * 0.03125f;
                sv[j] = v;
                tmax = fmaxf(tmax, v);
            }
            tmax = fmaxf(tmax, __shfl_xor_sync(0xffffffffu, tmax, 1));
            tmax = fmaxf(tmax, __shfl_xor_sync(0xffffffffu, tmax, 2));
            float mn = fmaxf(mrow, tmax);
            float corr = __expf(mrow - mn);
            mrow = mn;
            lrow *= corr; slo *= corr; shi *= corr;
            if (seg == 0) CR[sq] = corr;
            #pragma unroll
            for (int j = 0; j < 16; j++) {
                // hybrid exp: ~1/3 of elements on the FMA-pipe polynomial
                float e = ((j % 3) == 1) ? fexp(sv[j] - mn) : __expf(sv[j] - mn);
                lrow += e;
                int diff = kb + j - qg;
                if (diff <= -CLIPV)      slo += e;
                else if (diff >= CLIPV)  shi += e;
                else                     RB[sq*32 + diff + CLIPV - 1] = sv[j]; // raw score
                sv[j] = e;
            }
            #pragma unroll
            for (int u = 0; u < 4; u++)
                *(float4*)&Ps[sq*KPAD + seg*16 + u*4] = *(const float4*)&sv[u*4];
        }
        __syncthreads();

        // ---- O = O*corr + P V   (warp: 16 rows x 32 d-dims)
        {
            const float cA = CR[rg*16 + g], cB = CR[rg*16 + g + 8];
            #pragma unroll
            for (int nt = 0; nt < 4; nt++) {
                o[nt][0] *= cA; o[nt][1] *= cA;
                o[nt][2] *= cB; o[nt][3] *= cB;
            }
            const int r0 = rg * 16;
            #pragma unroll
            for (int ks = 0; ks < 8; ks++) {
                uint32_t pa0 = __float_as_uint(Ps[(r0+g  )*KPAD + ks*8 + t    ]);
                uint32_t pa1 = __float_as_uint(Ps[(r0+g+8)*KPAD + ks*8 + t    ]);
                uint32_t pa2 = __float_as_uint(Ps[(r0+g  )*KPAD + ks*8 + t + 4]);
                uint32_t pa3 = __float_as_uint(Ps[(r0+g+8)*KPAD + ks*8 + t + 4]);
                #pragma unroll
                for (int nt = 0; nt < 4; nt++) {
                    const int d = cg*32 + nt*8 + g;
                    uint32_t b0 = __float_as_uint(Vs[(ks*8 + t    )*VPAD + d]);
                    uint32_t b1 = __float_as_uint(Vs[(ks*8 + t + 4)*VPAD + d]);
                    mma_tf32(o[nt][0], o[nt][1], o[nt][2], o[nt][3],
                             pa0, pa1, pa2, pa3, b0, b1);
                }
            }
        }
        __syncthreads();
    }

    // ---- write O frags to smem for thread-layout epilogue
    {
        const int r0 = rg*16 + g;
        #pragma unroll
        for (int nt = 0; nt < 4; nt++) {
            const int col = cg*32 + nt*8 + 2*t;
            *(float2*)&Ps[ r0     *KPAD + col] = make_float2(o[nt][0], o[nt][1]);
            *(float2*)&Ps[(r0 + 8)*KPAD + col] = make_float2(o[nt][2], o[nt][3]);
        }
    }
    __syncthreads();

    // ---- final row-stat reduce (quad)
    lrow += __shfl_xor_sync(0xffffffffu, lrow, 1);
    lrow += __shfl_xor_sync(0xffffffffu, lrow, 2);
    slo  += __shfl_xor_sync(0xffffffffu, slo, 1);
    slo  += __shfl_xor_sync(0xffffffffu, slo, 2);
    shi  += __shfl_xor_sync(0xffffffffu, shi, 1);
    shi  += __shfl_xor_sync(0xffffffffu, shi, 2);

    // ---- epilogue: rel-value contributions (weights = exp(score - m_final))
    {
        float O[16];
        #pragma unroll
        for (int u = 0; u < 4; u++)
            *(float4*)&O[u*4] = *(const float4*)&Ps[sq*KPAD + seg*16 + u*4];
        const int cb = seg * 16;
        #pragma unroll
        for (int j = 0; j < 16; j++)
            O[j] += slo * RV[0*64 + cb + j] + shi * RV[32*64 + cb + j];
        for (int dd = 1; dd < 32; dd++) {
            float w = __expf(RB[sq*32 + dd - 1] - mrow);
            #pragma unroll
            for (int j = 0; j < 16; j++)
                O[j] = fmaf(w, RV[dd*64 + cb + j], O[j]);
        }
        const float inv = 1.0f / lrow;
        const int bb = bh >> 4, h = bh & 15;
        float* dst = &g_ctx[((size_t)(bb * SEQ + q0 + sq)) * DKEY + h * HDIM + cb];
        #pragma unroll
        for (int u = 0; u < 4; u++) {
            float4 v = make_float4(O[u*4+0]*inv, O[u*4+1]*inv, O[u*4+2]*inv, O[u*4+3]*inv);
            *(float4*)&dst[u*4] = v;
        }
    }
}

// ---------------------------------------------------------------------------
extern "C" void kernel_launch(void* const* d_in, const int* in_sizes, int n_in,
                              void* d_out, int out_size)
{
    (void)in_sizes; (void)n_in; (void)out_size;
    const float* q    = (const float*)d_in[0];
    const float* k    = (const float*)d_in[1];
    const float* v    = (const float*)d_in[2];
    const float* Wq   = (const float*)d_in[3];
    const float* bq   = (const float*)d_in[4];
    const float* Wk   = (const float*)d_in[5];
    const float* bk   = (const float*)d_in[6];
    const float* Wv   = (const float*)d_in[7];
    const float* bv   = (const float*)d_in[8];
    const float* Wo   = (const float*)d_in[9];
    const float* bo   = (const float*)d_in[10];
    const float* relk = (const float*)d_in[11];
    const float* relv = (const float*)d_in[12];
    float* out = (float*)d_out;

    float *qh, *kh, *vh, *ctx;
    cudaGetSymbolAddress((void**)&qh, g_qh);
    cudaGetSymbolAddress((void**)&kh, g_kh);
    cudaGetSymbolAddress((void**)&vh, g_vh);
    cudaGetSymbolAddress((void**)&ctx, g_ctx);

    cudaFuncSetAttribute(proj_mma, cudaFuncAttributeMaxDynamicSharedMemorySize, PSMEM);
    cudaFuncSetAttribute(attn_mma, cudaFuncAttributeMaxDynamicSharedMemorySize, AS_TOT * 4);

    dim3 gProj(DKEY / 128, MROWS / 128);   // (8, 32)
    proj_mma<<<gProj, 256, PSMEM>>>(q, Wq, bq, qh, 1);
    proj_mma<<<gProj, 256, PSMEM>>>(k, Wk, bk, kh, 1);
    proj_mma<<<gProj, 256, PSMEM>>>(v, Wv, bv, vh, 1);

    dim3 gAttn(SEQ / 64, BH);              // (32, 32)
    attn_mma<<<gAttn, 256, AS_TOT * 4>>>(relk, relv);

    proj_mma<<<gProj, 256, PSMEM>>>(ctx, Wo, bo, out, 0);
}

// round 11
// speedup vs baseline: 1.5954x; 1.5954x over previous
#include <cuda_runtime.h>
#include <cuda_fp16.h>
#include <cstdint>

// ---------------------------------------------------------------------------
// MultiHeadAttention w/ Shaw relative position. B=2, L=2048, E=1024, H=16,
// hd=64, clip=16.  compute_103 path -> mma.sync tensor cores.
//  1) q/k/v projections + ReLU: mma.sync tf32 GEMM -> split-head [BH][L][64]
//  2) flash attention (qrel fused): S=QK^T / O=PV on mma.sync.m16n8k16.f16
//     (fp16 mantissa == tf32 mantissa; V,P >= 0 so no cancellation).
//     CTA = 64 q-rows x 64 k-tile, 256 threads, 2 CTA/SM.
//  3) out projection + ReLU: mma.sync tf32 GEMM
// ---------------------------------------------------------------------------

#define BATCH  2
#define SEQ    2048
#define EMB    1024
#define NHEADS 16
#define HDIM   64
#define DKEY   1024
#define CLIPV  16
#define ND     33
#define MROWS  (BATCH*SEQ)
#define BH     (BATCH*NHEADS)

__device__ __align__(256) float g_qh[BH*SEQ*HDIM];
__device__ __align__(256) float g_kh[BH*SEQ*HDIM];
__device__ __align__(256) float g_vh[BH*SEQ*HDIM];
__device__ __align__(256) float g_ctx[MROWS*DKEY];

__device__ __forceinline__ float tf32r(float x) {
    asm("cvt.rna.tf32.f32 %0, %0;" : "+f"(x));
    return x;
}
__device__ __forceinline__ void mma_tf32(
    float& d0, float& d1, float& d2, float& d3,
    uint32_t a0, uint32_t a1, uint32_t a2, uint32_t a3,
    uint32_t b0, uint32_t b1)
{
    asm volatile(
        "mma.sync.aligned.m16n8k8.row.col.f32.tf32.tf32.f32 "
        "{%0,%1,%2,%3}, {%4,%5,%6,%7}, {%8,%9}, {%0,%1,%2,%3};"
        : "+f"(d0), "+f"(d1), "+f"(d2), "+f"(d3)
        : "r"(a0), "r"(a1), "r"(a2), "r"(a3), "r"(b0), "r"(b1));
}
__device__ __forceinline__ void mma_f16(
    float& d0, float& d1, float& d2, float& d3,
    uint32_t a0, uint32_t a1, uint32_t a2, uint32_t a3,
    uint32_t b0, uint32_t b1)
{
    asm volatile(
        "mma.sync.aligned.m16n8k16.row.col.f32.f16.f16.f32 "
        "{%0,%1,%2,%3}, {%4,%5,%6,%7}, {%8,%9}, {%0,%1,%2,%3};"
        : "+f"(d0), "+f"(d1), "+f"(d2), "+f"(d3)
        : "r"(a0), "r"(a1), "r"(a2), "r"(a3), "r"(b0), "r"(b1));
}
__device__ __forceinline__ uint32_t h2u(__half2 h) { return *(uint32_t*)&h; }

// ---------------------------------------------------------------------------
// mma.sync tf32 GEMM projections (validated R7). CTA 128x128, BK=16.
// ---------------------------------------------------------------------------
#define PM_PAD 20
#define PM_BUF (128 * PM_PAD)
#define PSMEM  (4 * PM_BUF * 4)

__global__ void __launch_bounds__(256) proj_mma(
    const float* __restrict__ X, const float* __restrict__ W,
    const float* __restrict__ bias, float* __restrict__ out, int split)
{
    extern __shared__ float smf[];
    float* As = smf;
    float* Bs = smf + 2 * PM_BUF;

    const int tid = threadIdx.x;
    const int lane = tid & 31, wid = tid >> 5;
    const int wm = wid & 3, wn = wid >> 2;
    const int lr = lane >> 2, lq = lane & 3;
    const int m0 = blockIdx.y * 128, n0 = blockIdx.x * 128;

    const float4* X4 = (const float4*)X;
    const float4* W4 = (const float4*)W;

    const int r0 = tid >> 2, c0 = tid & 3;
    const int r1 = (tid + 256) >> 2, c1 = tid & 3;

    float c[2][8][4];
    #pragma unroll
    for (int i = 0; i < 2; i++)
        #pragma unroll
        for (int j = 0; j < 8; j++)
            #pragma unroll
            for (int t = 0; t < 4; t++) c[i][j][t] = 0.f;

    {
        float4 xa0 = X4[(size_t)(m0 + r0) * 256 + c0];
        float4 xa1 = X4[(size_t)(m0 + r1) * 256 + c1];
        float4 wb0 = W4[(size_t)(n0 + r0) * 256 + c0];
        float4 wb1 = W4[(size_t)(n0 + r1) * 256 + c1];
        float* a = As; float* b = Bs;
        a[r0*PM_PAD + c0*4+0] = tf32r(xa0.x); a[r0*PM_PAD + c0*4+1] = tf32r(xa0.y);
        a[r0*PM_PAD + c0*4+2] = tf32r(xa0.z); a[r0*PM_PAD + c0*4+3] = tf32r(xa0.w);
        a[r1*PM_PAD + c1*4+0] = tf32r(xa1.x); a[r1*PM_PAD + c1*4+1] = tf32r(xa1.y);
        a[r1*PM_PAD + c1*4+2] = tf32r(xa1.z); a[r1*PM_PAD + c1*4+3] = tf32r(xa1.w);
        b[r0*PM_PAD + c0*4+0] = tf32r(wb0.x); b[r0*PM_PAD + c0*4+1] = tf32r(wb0.y);
        b[r0*PM_PAD + c0*4+2] = tf32r(wb0.z); b[r0*PM_PAD + c0*4+3] = tf32r(wb0.w);
        b[r1*PM_PAD + c1*4+0] = tf32r(wb1.x); b[r1*PM_PAD + c1*4+1] = tf32r(wb1.y);
        b[r1*PM_PAD + c1*4+2] = tf32r(wb1.z); b[r1*PM_PAD + c1*4+3] = tf32r(wb1.w);
    }
    __syncthreads();

    for (int kc = 0; kc < 64; kc++) {
        const int buf = kc & 1;
        float4 xa0, xa1, wb0, wb1;
        if (kc + 1 < 64) {
            const int kb = (kc + 1) * 4;
            xa0 = X4[(size_t)(m0 + r0) * 256 + kb + c0];
            xa1 = X4[(size_t)(m0 + r1) * 256 + kb + c1];
            wb0 = W4[(size_t)(n0 + r0) * 256 + kb + c0];
            wb1 = W4[(size_t)(n0 + r1) * 256 + kb + c1];
        }

        const float* a = As + buf * PM_BUF;
        const float* b = Bs + buf * PM_BUF;
        #pragma unroll
        for (int ks = 0; ks < 2; ks++) {
            const int k0 = ks * 8 + lq;
            uint32_t af[2][4];
            #pragma unroll
            for (int mt = 0; mt < 2; mt++) {
                const int row = wm * 32 + mt * 16 + lr;
                af[mt][0] = __float_as_uint(a[row * PM_PAD + k0]);
                af[mt][1] = __float_as_uint(a[(row + 8) * PM_PAD + k0]);
                af[mt][2] = __float_as_uint(a[row * PM_PAD + k0 + 4]);
                af[mt][3] = __float_as_uint(a[(row + 8) * PM_PAD + k0 + 4]);
            }
            #pragma unroll
            for (int nt = 0; nt < 8; nt++) {
                const int col = wn * 64 + nt * 8 + lr;
                uint32_t b0 = __float_as_uint(b[col * PM_PAD + k0]);
                uint32_t b1 = __float_as_uint(b[col * PM_PAD + k0 + 4]);
                #pragma unroll
                for (int mt = 0; mt < 2; mt++)
                    mma_tf32(c[mt][nt][0], c[mt][nt][1], c[mt][nt][2], c[mt][nt][3],
                             af[mt][0], af[mt][1], af[mt][2], af[mt][3], b0, b1);
            }
        }

        if (kc + 1 < 64) {
            float* an = As + (buf ^ 1) * PM_BUF;
            float* bn = Bs + (buf ^ 1) * PM_BUF;
            an[r0*PM_PAD + c0*4+0] = tf32r(xa0.x); an[r0*PM_PAD + c0*4+1] = tf32r(xa0.y);
            an[r0*PM_PAD + c0*4+2] = tf32r(xa0.z); an[r0*PM_PAD + c0*4+3] = tf32r(xa0.w);
            an[r1*PM_PAD + c1*4+0] = tf32r(xa1.x); an[r1*PM_PAD + c1*4+1] = tf32r(xa1.y);
            an[r1*PM_PAD + c1*4+2] = tf32r(xa1.z); an[r1*PM_PAD + c1*4+3] = tf32r(xa1.w);
            bn[r0*PM_PAD + c0*4+0] = tf32r(wb0.x); bn[r0*PM_PAD + c0*4+1] = tf32r(wb0.y);
            bn[r0*PM_PAD + c0*4+2] = tf32r(wb0.z); bn[r0*PM_PAD + c0*4+3] = tf32r(wb0.w);
            bn[r1*PM_PAD + c1*4+0] = tf32r(wb1.x); bn[r1*PM_PAD + c1*4+1] = tf32r(wb1.y);
            bn[r1*PM_PAD + c1*4+2] = tf32r(wb1.z); bn[r1*PM_PAD + c1*4+3] = tf32r(wb1.w);
        }
        __syncthreads();
    }

    #pragma unroll
    for (int mt = 0; mt < 2; mt++) {
        #pragma unroll
        for (int nt = 0; nt < 8; nt++) {
            const int row = m0 + wm * 32 + mt * 16 + lr;
            const int col = n0 + wn * 64 + nt * 8 + 2 * lq;
            const float bia0 = bias[col], bia1 = bias[col + 1];
            #pragma unroll
            for (int half = 0; half < 2; half++) {
                const int m = row + half * 8;
                float v0 = fmaxf(c[mt][nt][half * 2 + 0] + bia0, 0.f);
                float v1 = fmaxf(c[mt][nt][half * 2 + 1] + bia1, 0.f);
                if (split) {
                    const int bb = m >> 11, ll = m & (SEQ - 1);
                    const int h = col >> 6, d = col & 63;
                    out[(((size_t)(bb * NHEADS + h)) * SEQ + ll) * HDIM + d]     = v0;
                    out[(((size_t)(bb * NHEADS + h)) * SEQ + ll) * HDIM + d + 1] = v1;
                } else {
                    float2 v = make_float2(v0, v1);
                    *(float2*)&out[(size_t)m * DKEY + col] = v;
                }
            }
        }
    }
}

// ---------------------------------------------------------------------------
// Flash attention, fp16 mma m16n8k16, qrel fused.
// CTA: 64 q-rows x 64 k-tile, 256 thr = 8 warps (4 rowgroups x 2 halves).
// S buffer (fp32, stride 68) aliases Q staging. K/Vt/P fp16 stride 72 halves
// (36 words == 4 mod 32 -> conflict-free 4g+t fragment residues).
// ---------------------------------------------------------------------------
#define SB_S   0        // fp32 64x68 = 17408 B (Q staging, then S/O)
#define SB_K   17408    // fp16 64x72 = 9216 B
#define SB_VT  26624    // fp16 64x72 (Vt[d][key]) = 9216 B
#define SB_P   35840    // fp16 64x72 = 9216 B (prologue: rel_k fp32 33x68)
#define SB_QR  45056    // fp32 64x33 = 8448 B
#define SB_RB  53504    // fp32 64x32 = 8192 B
#define SB_RV  61696    // fp32 33x64 = 8448 B
#define SB_CR  70144    // fp32 64 = 256 B
#define SB_TOT 70400

__global__ void __launch_bounds__(256, 2) attn_mma(
    const float* __restrict__ rel_k, const float* __restrict__ rel_v)
{
    extern __shared__ char smc[];
    float*    Sb  = (float*)(smc + SB_S);
    uint32_t* Kw  = (uint32_t*)(smc + SB_K);
    __half*   Vth = (__half*)(smc + SB_VT);
    uint32_t* Vtw = (uint32_t*)(smc + SB_VT);
    uint32_t* Pw  = (uint32_t*)(smc + SB_P);
    float*    QR  = (float*)(smc + SB_QR);
    float*    RB  = (float*)(smc + SB_RB);
    float*    RV  = (float*)(smc + SB_RV);
    float*    CR  = (float*)(smc + SB_CR);

    const int tid = threadIdx.x;
    const int lane = tid & 31, wid = tid >> 5;
    const int g = lane >> 2, t = lane & 3;
    const int rg = wid >> 1;          // row group (16 rows)
    const int cg = wid & 1;           // column half
    const int bh = blockIdx.y, q0 = blockIdx.x * 64;
    const int sq = tid >> 2;          // softmax row
    const int seg = tid & 3;          // 16-col segment

    // ---- prologue: Q (fp32, stride 68), rel_k -> P region (fp32, stride 68),
    //      rel_v -> RV, RB = -inf
    const float4* q4 = (const float4*)(g_qh + ((size_t)bh * SEQ + q0) * HDIM);
    for (int i = tid; i < 1024; i += 256) {
        int r = i >> 4, cc = (i & 15) << 2;
        *(float4*)&Sb[r*68 + cc] = q4[i];
    }
    {
        float* rkf = (float*)(smc + SB_P);
        const float4* rk4 = (const float4*)rel_k;
        const float4* rv4 = (const float4*)rel_v;
        for (int i = tid; i < ND * 16; i += 256) {
            int r = i >> 4, cc = (i & 15) << 2;
            *(float4*)&rkf[r*68 + cc] = rk4[i];
            ((float4*)RV)[i] = rv4[i];
        }
    }
    for (int i = tid; i < 64 * 32; i += 256) RB[i] = -1e30f;
    __syncthreads();

    // ---- fused qrel: QR[q][d] = Sb(Q)[q][:] . rel_k[d][:]
    {
        const float* rkf = (const float*)(smc + SB_P);
        for (int i = tid; i < 64 * ND; i += 256) {
            int q = i / ND, d = i - q * ND;
            float s = 0.f;
            #pragma unroll 8
            for (int cc = 0; cc < 64; cc++) s = fmaf(Sb[q*68 + cc], rkf[d*68 + cc], s);
            QR[q*ND + d] = s;
        }
    }

    // ---- preload Q fragments as fp16 (warp rows rg*16 + {g, g+8})
    uint32_t qa[4][4];
    {
        const int rb = rg * 16;
        #pragma unroll
        for (int ks = 0; ks < 4; ks++) {
            const int k0 = ks * 16;
            qa[ks][0] = h2u(__floats2half2_rn(Sb[(rb+g  )*68 + k0 + 2*t    ], Sb[(rb+g  )*68 + k0 + 2*t + 1]));
            qa[ks][1] = h2u(__floats2half2_rn(Sb[(rb+g+8)*68 + k0 + 2*t    ], Sb[(rb+g+8)*68 + k0 + 2*t + 1]));
            qa[ks][2] = h2u(__floats2half2_rn(Sb[(rb+g  )*68 + k0 + 2*t + 8], Sb[(rb+g  )*68 + k0 + 2*t + 9]));
            qa[ks][3] = h2u(__floats2half2_rn(Sb[(rb+g+8)*68 + k0 + 2*t + 8], Sb[(rb+g+8)*68 + k0 + 2*t + 9]));
        }
    }

    float o[4][4] = {};
    float mrow = -1e30f, lrow = 0.f, slo = 0.f, shi = 0.f;

    for (int kt = 0; kt < SEQ / 64; kt++) {
        // ---- stage K (fp16 row-major) and V transposed (Vt[d][key], fp16)
        const float4* k4 = (const float4*)(g_kh + ((size_t)bh * SEQ + kt*64) * HDIM);
        const float4* v4 = (const float4*)(g_vh + ((size_t)bh * SEQ + kt*64) * HDIM);
        for (int i = tid; i < 1024; i += 256) {
            int r = i >> 4, db = (i & 15) << 2;
            float4 kv = k4[i];
            __half2 h0 = __floats2half2_rn(kv.x, kv.y);
            __half2 h1 = __floats2half2_rn(kv.z, kv.w);
            ((uint2*)(smc + SB_K))[r*18 + (db >> 2)] = make_uint2(h2u(h0), h2u(h1));
            float4 vv = v4[i];
            Vth[(db+0)*72 + r] = __float2half_rn(vv.x);
            Vth[(db+1)*72 + r] = __float2half_rn(vv.y);
            Vth[(db+2)*72 + r] = __float2half_rn(vv.z);
            Vth[(db+3)*72 + r] = __float2half_rn(vv.w);
        }
        __syncthreads();   // also orders qrel/Q-preload before S overwrite

        // ---- S = Q K^T  (warp: 16 rows x 32 cols, fp16 mma)
        float s[4][4] = {};
        #pragma unroll
        for (int ks = 0; ks < 4; ks++) {
            #pragma unroll
            for (int nt = 0; nt < 4; nt++) {
                const int col = cg*32 + nt*8 + g;
                uint32_t b0 = Kw[col*36 + ks*8 + t];
                uint32_t b1 = Kw[col*36 + ks*8 + t + 4];
                mma_f16(s[nt][0], s[nt][1], s[nt][2], s[nt][3],
                        qa[ks][0], qa[ks][1], qa[ks][2], qa[ks][3], b0, b1);
            }
        }
        {
            const int r0 = rg*16 + g;
            #pragma unroll
            for (int nt = 0; nt < 4; nt++) {
                const int col = cg*32 + nt*8 + 2*t;
                *(float2*)&Sb[ r0     *68 + col] = make_float2(s[nt][0], s[nt][1]);
                *(float2*)&Sb[(r0 + 8)*68 + col] = make_float2(s[nt][2], s[nt][3]);
            }
        }
        __syncthreads();

        // ---- softmax + Shaw-rel bookkeeping (thread = row sq, 16 cols)
        {
            const int kb = kt*64 + seg*16;
            const int qg = q0 + sq;
            float sv[16];
            #pragma unroll
            for (int u = 0; u < 4; u++)
                *(float4*)&sv[u*4] = *(const float4*)&Sb[sq*68 + seg*16 + u*4];
            float tmax = -1e30f;
            #pragma unroll
            for (int j = 0; j < 16; j++) {
                int diff = kb + j - qg;
                int dcl = diff < -CLIPV ? 0 : (diff > CLIPV ? 2*CLIPV : diff + CLIPV);
                float v = (sv[j] + QR[sq*ND + dcl]) * 0.03125f;
                sv[j] = v;
                tmax = fmaxf(tmax, v);
            }
            tmax = fmaxf(tmax, __shfl_xor_sync(0xffffffffu, tmax, 1));
            tmax = fmaxf(tmax, __shfl_xor_sync(0xffffffffu, tmax, 2));
            float mn = fmaxf(mrow, tmax);
            float corr = __expf(mrow - mn);
            mrow = mn;
            lrow *= corr; slo *= corr; shi *= corr;
            if (seg == 0) CR[sq] = corr;
            #pragma unroll
            for (int j = 0; j < 16; j++) {
                float e = __expf(sv[j] - mn);
                lrow += e;
                int diff = kb + j - qg;
                if (diff <= -CLIPV)      slo += e;
                else if (diff >= CLIPV)  shi += e;
                else                     RB[sq*32 + diff + CLIPV - 1] = sv[j]; // raw score
                sv[j] = e;
            }
            #pragma unroll
            for (int u = 0; u < 8; u++)
                Pw[sq*36 + seg*8 + u] = h2u(__floats2half2_rn(sv[2*u], sv[2*u+1]));
        }
        __syncthreads();

        // ---- O = O*corr + P V   (fp16 mma; B from Vt)
        {
            const float cA = CR[rg*16 + g], cB = CR[rg*16 + g + 8];
            #pragma unroll
            for (int nt = 0; nt < 4; nt++) {
                o[nt][0] *= cA; o[nt][1] *= cA;
                o[nt][2] *= cB; o[nt][3] *= cB;
            }
            const int r0 = rg * 16;
            #pragma unroll
            for (int ks = 0; ks < 4; ks++) {
                uint32_t pa0 = Pw[(r0+g  )*36 + ks*8 + t];
                uint32_t pa1 = Pw[(r0+g+8)*36 + ks*8 + t];
                uint32_t pa2 = Pw[(r0+g  )*36 + ks*8 + t + 4];
                uint32_t pa3 = Pw[(r0+g+8)*36 + ks*8 + t + 4];
                #pragma unroll
                for (int nt = 0; nt < 4; nt++) {
                    const int d = cg*32 + nt*8 + g;
                    uint32_t b0 = Vtw[d*36 + ks*8 + t];
                    uint32_t b1 = Vtw[d*36 + ks*8 + t + 4];
                    mma_f16(o[nt][0], o[nt][1], o[nt][2], o[nt][3],
                            pa0, pa1, pa2, pa3, b0, b1);
                }
            }
        }
        __syncthreads();
    }

    // ---- write O frags to S buffer for thread-layout epilogue
    {
        const int r0 = rg*16 + g;
        #pragma unroll
        for (int nt = 0; nt < 4; nt++) {
            const int col = cg*32 + nt*8 + 2*t;
            *(float2*)&Sb[ r0     *68 + col] = make_float2(o[nt][0], o[nt][1]);
            *(float2*)&Sb[(r0 + 8)*68 + col] = make_float2(o[nt][2], o[nt][3]);
        }
    }
    __syncthreads();

    // ---- final row-stat reduce (quad)
    lrow += __shfl_xor_sync(0xffffffffu, lrow, 1);
    lrow += __shfl_xor_sync(0xffffffffu, lrow, 2);
    slo  += __shfl_xor_sync(0xffffffffu, slo, 1);
    slo  += __shfl_xor_sync(0xffffffffu, slo, 2);
    shi  += __shfl_xor_sync(0xffffffffu, shi, 1);
    shi  += __shfl_xor_sync(0xffffffffu, shi, 2);

    // ---- epilogue: rel-value contributions (weights = exp(score - m_final))
    {
        float O[16];
        #pragma unroll
        for (int u = 0; u < 4; u++)
            *(float4*)&O[u*4] = *(const float4*)&Sb[sq*68 + seg*16 + u*4];
        const int cb = seg * 16;
        #pragma unroll
        for (int j = 0; j < 16; j++)
            O[j] += slo * RV[0*64 + cb + j] + shi * RV[32*64 + cb + j];
        for (int dd = 1; dd < 32; dd++) {
            float w = __expf(RB[sq*32 + dd - 1] - mrow);
            #pragma unroll
            for (int j = 0; j < 16; j++)
                O[j] = fmaf(w, RV[dd*64 + cb + j], O[j]);
        }
        const float inv = 1.0f / lrow;
        const int bb = bh >> 4, h = bh & 15;
        float* dst = &g_ctx[((size_t)(bb * SEQ + q0 + sq)) * DKEY + h * HDIM + cb];
        #pragma unroll
        for (int u = 0; u < 4; u++) {
            float4 v = make_float4(O[u*4+0]*inv, O[u*4+1]*inv, O[u*4+2]*inv, O[u*4+3]*inv);
            *(float4*)&dst[u*4] = v;
        }
    }
}

// ---------------------------------------------------------------------------
extern "C" void kernel_launch(void* const* d_in, const int* in_sizes, int n_in,
                              void* d_out, int out_size)
{
    (void)in_sizes; (void)n_in; (void)out_size;
    const float* q    = (const float*)d_in[0];
    const float* k    = (const float*)d_in[1];
    const float* v    = (const float*)d_in[2];
    const float* Wq   = (const float*)d_in[3];
    const float* bq   = (const float*)d_in[4];
    const float* Wk   = (const float*)d_in[5];
    const float* bk   = (const float*)d_in[6];
    const float* Wv   = (const float*)d_in[7];
    const float* bv   = (const float*)d_in[8];
    const float* Wo   = (const float*)d_in[9];
    const float* bo   = (const float*)d_in[10];
    const float* relk = (const float*)d_in[11];
    const float* relv = (const float*)d_in[12];
    float* out = (float*)d_out;

    float *qh, *kh, *vh, *ctx;
    cudaGetSymbolAddress((void**)&qh, g_qh);
    cudaGetSymbolAddress((void**)&kh, g_kh);
    cudaGetSymbolAddress((void**)&vh, g_vh);
    cudaGetSymbolAddress((void**)&ctx, g_ctx);

    cudaFuncSetAttribute(proj_mma, cudaFuncAttributeMaxDynamicSharedMemorySize, PSMEM);
    cudaFuncSetAttribute(attn_mma, cudaFuncAttributeMaxDynamicSharedMemorySize, SB_TOT);

    dim3 gProj(DKEY / 128, MROWS / 128);   // (8, 32)
    proj_mma<<<gProj, 256, PSMEM>>>(q, Wq, bq, qh, 1);
    proj_mma<<<gProj, 256, PSMEM>>>(k, Wk, bk, kh, 1);
    proj_mma<<<gProj, 256, PSMEM>>>(v, Wv, bv, vh, 1);

    dim3 gAttn(SEQ / 64, BH);              // (32, 32)
    attn_mma<<<gAttn, 256, SB_TOT>>>(relk, relv);

    proj_mma<<<gProj, 256, PSMEM>>>(ctx, Wo, bo, out, 0);
}